// round 4
// baseline (speedup 1.0000x reference)
#include <cuda_runtime.h>

// ---------------------------------------------------------------------------
// NeuralODEModel: persistent dopri5, f32x2-packed, TWO rows per thread.
// Weight LDS (the R3 bottleneck: L1=90%) amortized over 2 rows sharing the
// same loaded weight registers. k1..k4 spilled to private SMEM slots to keep
// register pressure ~220. BLOCK=128 x GRID=128 x 2 rows = 32768 exactly.
// ---------------------------------------------------------------------------

#define B_TOTAL 32768
#define T_STEPS 64
#define N_INJ   8
#define SID     7
#define SHD     16
#define OHD     16
#define MID     64
#define BLOCK   128
#define GRID    128
#define RPC     256   // rows per CTA (2 per thread)

// Shared memory layout (float offsets)
#define S_W1Y 0                      // [64][16] W1 rows 0..15 transposed
#define S_W2  1024                   // [64][16]
#define S_W1D 2048                   // [64]
#define S_B2  2112                   // [16]
#define S_WR  2128                   // [16]
#define S_T   2144                   // [64]
#define S_BR  2208                   // [1]
#define S_CG  2560                   // [64][128] u64 (cA,cB) -> 16384 floats
#define S_KS  (S_CG + 16384)         // [4][16][128] u64 k-spill -> 16384 floats
#define S_TOTAL (S_KS + 16384)       // 35328 floats = 141312 bytes

typedef unsigned long long u64;

__device__ __forceinline__ u64 pk2(float lo, float hi) {
    u64 r; asm("mov.b64 %0,{%1,%2};" : "=l"(r) : "f"(lo), "f"(hi)); return r;
}
__device__ __forceinline__ u64 pks(float x) { return pk2(x, x); }
__device__ __forceinline__ void upk(u64 v, float& lo, float& hi) {
    asm("mov.b64 {%0,%1},%2;" : "=f"(lo), "=f"(hi) : "l"(v));
}
__device__ __forceinline__ u64 f2fma(u64 a, u64 b, u64 c) {
    u64 d; asm("fma.rn.f32x2 %0,%1,%2,%3;" : "=l"(d) : "l"(a), "l"(b), "l"(c)); return d;
}
__device__ __forceinline__ u64 f2mul(u64 a, u64 b) {
    u64 d; asm("mul.rn.f32x2 %0,%1,%2;" : "=l"(d) : "l"(a), "l"(b)); return d;
}
__device__ __forceinline__ u64 f2add(u64 a, u64 b) {
    u64 d; asm("add.rn.f32x2 %0,%1,%2;" : "=l"(d) : "l"(a), "l"(b)); return d;
}
__device__ __forceinline__ float tanhap(float x) {
    float r; asm("tanh.approx.f32 %0,%1;" : "=f"(r) : "f"(x)); return r;
}

// ---- one MLP eval for BOTH rows (shared weight loads) ---------------------
__device__ __forceinline__ void f_eval2(
    float tv,
    const u64* __restrict__ yA, const u64* __restrict__ yB,   // [8] each
    u64* __restrict__ kA, u64* __restrict__ kB,               // [8] each
    const float* __restrict__ sm, int tid,
    const float* __restrict__ itmA, const float* __restrict__ idnA,
    const float* __restrict__ itmB, const float* __restrict__ idnB)
{
    float doseA = 0.0f, doseB = 0.0f;
    #pragma unroll
    for (int n = 0; n < N_INJ; n++) {
        float dA = tv - itmA[n];
        float dB = tv - itmB[n];
        doseA += idnA[n] * __expf(-0.5f * dA * dA);
        doseB += idnB[n] * __expf(-0.5f * dB * dB);
    }
    doseA = fminf(fmaxf(doseA, 0.0f), 100.0f);
    doseB = fminf(fmaxf(doseB, 0.0f), 100.0f);

    const ulonglong2* __restrict__ w1y = (const ulonglong2*)(sm + S_W1Y);
    const ulonglong2* __restrict__ w2  = (const ulonglong2*)(sm + S_W2);
    const u64* __restrict__ cg = (const u64*)(sm + S_CG) + tid;
    const float* __restrict__ w1d = sm + S_W1D;
    const ulonglong2* __restrict__ b2p = (const ulonglong2*)(sm + S_B2);

    {
        ulonglong2 q0 = b2p[0], q1 = b2p[1], q2 = b2p[2], q3 = b2p[3];
        kA[0] = q0.x; kA[1] = q0.y; kA[2] = q1.x; kA[3] = q1.y;
        kA[4] = q2.x; kA[5] = q2.y; kA[6] = q3.x; kA[7] = q3.y;
        kB[0] = q0.x; kB[1] = q0.y; kB[2] = q1.x; kB[3] = q1.y;
        kB[4] = q2.x; kB[5] = q2.y; kB[6] = q3.x; kB[7] = q3.y;
    }

    #pragma unroll 2
    for (int j = 0; j < MID; j++) {
        u64 cab = cg[j * BLOCK];
        float cA, cB; upk(cab, cA, cB);
        float w1dj = w1d[j];
        float zA0 = fmaf(doseA, w1dj, cA);
        float zB0 = fmaf(doseB, w1dj, cB);

        ulonglong2 a0 = w1y[j * 4 + 0], a1 = w1y[j * 4 + 1];
        ulonglong2 a2 = w1y[j * 4 + 2], a3 = w1y[j * 4 + 3];

        u64 sA0 = f2fma(yA[0], a0.x, pk2(zA0, 0.0f));
        u64 sB0 = f2fma(yB[0], a0.x, pk2(zB0, 0.0f));
        u64 sA1 = f2mul(yA[1], a0.y);
        u64 sB1 = f2mul(yB[1], a0.y);
        sA0 = f2fma(yA[2], a1.x, sA0);  sB0 = f2fma(yB[2], a1.x, sB0);
        sA1 = f2fma(yA[3], a1.y, sA1);  sB1 = f2fma(yB[3], a1.y, sB1);
        sA0 = f2fma(yA[4], a2.x, sA0);  sB0 = f2fma(yB[4], a2.x, sB0);
        sA1 = f2fma(yA[5], a2.y, sA1);  sB1 = f2fma(yB[5], a2.y, sB1);
        sA0 = f2fma(yA[6], a3.x, sA0);  sB0 = f2fma(yB[6], a3.x, sB0);
        sA1 = f2fma(yA[7], a3.y, sA1);  sB1 = f2fma(yB[7], a3.y, sB1);

        u64 sA = f2add(sA0, sA1);
        u64 sB = f2add(sB0, sB1);
        float sAlo, sAhi, sBlo, sBhi;
        upk(sA, sAlo, sAhi); upk(sB, sBlo, sBhi);
        float aAct = tanhap(sAlo + sAhi);
        float bAct = tanhap(sBlo + sBhi);
        u64 aa = pks(aAct);
        u64 bb = pks(bAct);

        ulonglong2 v0 = w2[j * 4 + 0], v1 = w2[j * 4 + 1];
        ulonglong2 v2 = w2[j * 4 + 2], v3 = w2[j * 4 + 3];
        kA[0] = f2fma(aa, v0.x, kA[0]);  kB[0] = f2fma(bb, v0.x, kB[0]);
        kA[1] = f2fma(aa, v0.y, kA[1]);  kB[1] = f2fma(bb, v0.y, kB[1]);
        kA[2] = f2fma(aa, v1.x, kA[2]);  kB[2] = f2fma(bb, v1.x, kB[2]);
        kA[3] = f2fma(aa, v1.y, kA[3]);  kB[3] = f2fma(bb, v1.y, kB[3]);
        kA[4] = f2fma(aa, v2.x, kA[4]);  kB[4] = f2fma(bb, v2.x, kB[4]);
        kA[5] = f2fma(aa, v2.y, kA[5]);  kB[5] = f2fma(bb, v2.y, kB[5]);
        kA[6] = f2fma(aa, v3.x, kA[6]);  kB[6] = f2fma(bb, v3.x, kB[6]);
        kA[7] = f2fma(aa, v3.y, kA[7]);  kB[7] = f2fma(bb, v3.y, kB[7]);
    }
}

// k-spill helpers: slot in {0..3}, per-thread private, conflict-free
__device__ __forceinline__ void k_store(float* sm, int tid, int slot,
                                        const u64* kA, const u64* kB) {
    u64* ks = (u64*)(sm + S_KS);
    #pragma unroll
    for (int p = 0; p < 8; p++) {
        ks[(slot * 16 + p) * BLOCK + tid]     = kA[p];
        ks[(slot * 16 + 8 + p) * BLOCK + tid] = kB[p];
    }
}
__device__ __forceinline__ u64 k_ldA(const float* sm, int tid, int slot, int p) {
    return ((const u64*)(sm + S_KS))[(slot * 16 + p) * BLOCK + tid];
}
__device__ __forceinline__ u64 k_ldB(const float* sm, int tid, int slot, int p) {
    return ((const u64*)(sm + S_KS))[(slot * 16 + 8 + p) * BLOCK + tid];
}

extern "C" __global__ void __launch_bounds__(BLOCK, 1)
neural_ode_66236985639756(
    const float* __restrict__ t_g,
    const float* __restrict__ sf_g,
    const float* __restrict__ it_g,
    const float* __restrict__ id_g,
    const float* __restrict__ W_se, const float* __restrict__ b_se,
    const float* __restrict__ W_i,  const float* __restrict__ b_i,
    const float* __restrict__ W1,   const float* __restrict__ b1,
    const float* __restrict__ W2,   const float* __restrict__ b2,
    const float* __restrict__ Wr,   const float* __restrict__ br,
    float* __restrict__ out)
{
    extern __shared__ float sm[];
    const int tid = threadIdx.x;
    const int rA = blockIdx.x * RPC + tid;          // row A
    const int rB = rA + BLOCK;                      // row B

    // ---- cooperative SMEM init (shared weights only) ----------------------
    for (int idx = tid; idx < MID * 16; idx += BLOCK) {
        int j = idx >> 4, i = idx & 15;
        sm[S_W1Y + idx] = W1[i * MID + j];          // transpose rows 0..15
        sm[S_W2 + idx]  = W2[idx];
    }
    for (int idx = tid; idx < 64; idx += BLOCK) {
        sm[S_W1D + idx] = W1[32 * MID + idx];
        sm[S_T + idx]   = t_g[idx];
    }
    if (tid < 16) { sm[S_B2 + tid] = b2[tid]; sm[S_WR + tid] = Wr[tid]; }
    if (tid == 0) { sm[S_BR] = br[0]; }

    // ---- per-row static embed, h0, cg (both rows) -------------------------
    float seA[SHD], seB[SHD], hsA[OHD], hsB[OHD];
    {
        float sfv[SID];
        #pragma unroll
        for (int i = 0; i < SID; i++) sfv[i] = sf_g[rA * SID + i];
        #pragma unroll
        for (int o = 0; o < SHD; o++) {
            float acc = b_se[o];
            #pragma unroll
            for (int i = 0; i < SID; i++) acc += sfv[i] * W_se[i * SHD + o];
            seA[o] = fmaxf(acc, 0.0f);
        }
        #pragma unroll
        for (int i = 0; i < SID; i++) sfv[i] = sf_g[rB * SID + i];
        #pragma unroll
        for (int o = 0; o < SHD; o++) {
            float acc = b_se[o];
            #pragma unroll
            for (int i = 0; i < SID; i++) acc += sfv[i] * W_se[i * SHD + o];
            seB[o] = fmaxf(acc, 0.0f);
        }
    }
    #pragma unroll
    for (int o = 0; o < OHD; o++) {
        float aA = b_i[o], aB = b_i[o];
        #pragma unroll
        for (int i = 0; i < SHD; i++) {
            aA += seA[i] * W_i[i * OHD + o];
            aB += seB[i] * W_i[i * OHD + o];
        }
        hsA[o] = aA; hsB[o] = aB;
    }
    {
        u64* cgp = (u64*)(sm + S_CG);
        for (int j = 0; j < MID; j++) {
            float aA = b1[j], aB = b1[j];
            #pragma unroll
            for (int i = 0; i < SHD; i++) {
                float w = W1[(16 + i) * MID + j];
                aA += seA[i] * w;
                aB += seB[i] * w;
            }
            cgp[j * BLOCK + tid] = pk2(aA, aB);
        }
    }
    float itmA[N_INJ], idnA[N_INJ], itmB[N_INJ], idnB[N_INJ];
    #pragma unroll
    for (int n = 0; n < N_INJ; n++) {
        itmA[n] = it_g[rA * N_INJ + n];  idnA[n] = id_g[rA * N_INJ + n];
        itmB[n] = it_g[rB * N_INJ + n];  idnB[n] = id_g[rB * N_INJ + n];
    }
    __syncthreads();

    u64 hA[8], hB[8];
    #pragma unroll
    for (int p = 0; p < 8; p++) {
        hA[p] = pk2(hsA[2 * p], hsA[2 * p + 1]);
        hB[p] = pk2(hsB[2 * p], hsB[2 * p + 1]);
    }

    const ulonglong2* __restrict__ wrp = (const ulonglong2*)(sm + S_WR);

    // readout helper (inline twice via lambda-free macro-ish code)
    {
        ulonglong2 wr0 = wrp[0], wr1 = wrp[1], wr2 = wrp[2], wr3 = wrp[3];
        u64 accA = f2mul(hA[0], wr0.x);  u64 accB = f2mul(hB[0], wr0.x);
        accA = f2fma(hA[1], wr0.y, accA); accB = f2fma(hB[1], wr0.y, accB);
        accA = f2fma(hA[2], wr1.x, accA); accB = f2fma(hB[2], wr1.x, accB);
        accA = f2fma(hA[3], wr1.y, accA); accB = f2fma(hB[3], wr1.y, accB);
        accA = f2fma(hA[4], wr2.x, accA); accB = f2fma(hB[4], wr2.x, accB);
        accA = f2fma(hA[5], wr2.y, accA); accB = f2fma(hB[5], wr2.y, accB);
        accA = f2fma(hA[6], wr3.x, accA); accB = f2fma(hB[6], wr3.x, accB);
        accA = f2fma(hA[7], wr3.y, accA); accB = f2fma(hB[7], wr3.y, accB);
        float lo, hi; upk(accA, lo, hi);
        out[rA * T_STEPS] = fmaxf(sm[S_BR] + lo + hi, 0.0f);
        upk(accB, lo, hi);
        out[rB * T_STEPS] = fmaxf(sm[S_BR] + lo + hi, 0.0f);
    }

    const float A21 = 0.2f;
    const float A31 = 0.075f, A32 = 0.225f;
    const float A41 = (float)(44.0/45.0),      A42 = (float)(-56.0/15.0),
                A43 = (float)(32.0/9.0);
    const float A51 = (float)(19372.0/6561.0), A52 = (float)(-25360.0/2187.0),
                A53 = (float)(64448.0/6561.0), A54 = (float)(-212.0/729.0);
    const float A61 = (float)(9017.0/3168.0),  A62 = (float)(-355.0/33.0),
                A63 = (float)(46732.0/5247.0), A64 = (float)(49.0/176.0),
                A65 = (float)(-5103.0/18656.0);
    const float B1c = (float)(35.0/384.0),  B3c = (float)(500.0/1113.0),
                B4c = (float)(125.0/192.0), B5c = (float)(-2187.0/6784.0),
                B6c = (float)(11.0/84.0);
    const float C2 = 0.2f, C3 = 0.3f, C4 = 0.8f, C5 = (float)(8.0/9.0);

    u64 yA[8], yB[8], kAo[8], kBo[8], k5A[8], k5B[8];

    #pragma unroll 1
    for (int step = 0; step < T_STEPS - 1; ++step) {
        float t0 = sm[S_T + step], t1 = sm[S_T + step + 1];
        float dt = (t1 - t0) * 0.5f;
        #pragma unroll 1
        for (int sub = 0; sub < 2; ++sub) {
            float tv = t0 + sub * dt;

            // stage 1
            f_eval2(tv, hA, hB, kAo, kBo, sm, tid, itmA, idnA, itmB, idnB);
            k_store(sm, tid, 0, kAo, kBo);
            {
                u64 c = pks(dt * A21);
                #pragma unroll
                for (int p = 0; p < 8; p++) {
                    yA[p] = f2fma(c, kAo[p], hA[p]);
                    yB[p] = f2fma(c, kBo[p], hB[p]);
                }
            }
            // stage 2
            f_eval2(tv + C2 * dt, yA, yB, kAo, kBo, sm, tid, itmA, idnA, itmB, idnB);
            k_store(sm, tid, 1, kAo, kBo);
            {
                u64 c1 = pks(dt * A31), c2 = pks(dt * A32);
                #pragma unroll
                for (int p = 0; p < 8; p++) {
                    yA[p] = f2fma(c1, k_ldA(sm, tid, 0, p), f2fma(c2, kAo[p], hA[p]));
                    yB[p] = f2fma(c1, k_ldB(sm, tid, 0, p), f2fma(c2, kBo[p], hB[p]));
                }
            }
            // stage 3
            f_eval2(tv + C3 * dt, yA, yB, kAo, kBo, sm, tid, itmA, idnA, itmB, idnB);
            k_store(sm, tid, 2, kAo, kBo);
            {
                u64 c1 = pks(dt * A41), c2 = pks(dt * A42), c3 = pks(dt * A43);
                #pragma unroll
                for (int p = 0; p < 8; p++) {
                    u64 aA = f2fma(c3, kAo[p], hA[p]);
                    u64 aB = f2fma(c3, kBo[p], hB[p]);
                    aA = f2fma(c2, k_ldA(sm, tid, 1, p), aA);
                    aB = f2fma(c2, k_ldB(sm, tid, 1, p), aB);
                    yA[p] = f2fma(c1, k_ldA(sm, tid, 0, p), aA);
                    yB[p] = f2fma(c1, k_ldB(sm, tid, 0, p), aB);
                }
            }
            // stage 4
            f_eval2(tv + C4 * dt, yA, yB, kAo, kBo, sm, tid, itmA, idnA, itmB, idnB);
            k_store(sm, tid, 3, kAo, kBo);
            {
                u64 c1 = pks(dt * A51), c2 = pks(dt * A52),
                    c3 = pks(dt * A53), c4 = pks(dt * A54);
                #pragma unroll
                for (int p = 0; p < 8; p++) {
                    u64 aA = f2fma(c4, kAo[p], hA[p]);
                    u64 aB = f2fma(c4, kBo[p], hB[p]);
                    aA = f2fma(c3, k_ldA(sm, tid, 2, p), aA);
                    aB = f2fma(c3, k_ldB(sm, tid, 2, p), aB);
                    aA = f2fma(c2, k_ldA(sm, tid, 1, p), aA);
                    aB = f2fma(c2, k_ldB(sm, tid, 1, p), aB);
                    yA[p] = f2fma(c1, k_ldA(sm, tid, 0, p), aA);
                    yB[p] = f2fma(c1, k_ldB(sm, tid, 0, p), aB);
                }
            }
            // stage 5 (k5 stays in registers)
            f_eval2(tv + C5 * dt, yA, yB, k5A, k5B, sm, tid, itmA, idnA, itmB, idnB);
            {
                u64 c1 = pks(dt * A61), c2 = pks(dt * A62), c3 = pks(dt * A63),
                    c4 = pks(dt * A64), c5 = pks(dt * A65);
                #pragma unroll
                for (int p = 0; p < 8; p++) {
                    u64 aA = f2fma(c5, k5A[p], hA[p]);
                    u64 aB = f2fma(c5, k5B[p], hB[p]);
                    aA = f2fma(c4, k_ldA(sm, tid, 3, p), aA);
                    aB = f2fma(c4, k_ldB(sm, tid, 3, p), aB);
                    aA = f2fma(c3, k_ldA(sm, tid, 2, p), aA);
                    aB = f2fma(c3, k_ldB(sm, tid, 2, p), aB);
                    aA = f2fma(c2, k_ldA(sm, tid, 1, p), aA);
                    aB = f2fma(c2, k_ldB(sm, tid, 1, p), aB);
                    yA[p] = f2fma(c1, k_ldA(sm, tid, 0, p), aA);
                    yB[p] = f2fma(c1, k_ldB(sm, tid, 0, p), aB);
                }
            }
            // stage 6
            f_eval2(tv + dt, yA, yB, kAo, kBo, sm, tid, itmA, idnA, itmB, idnB);
            {
                u64 c1 = pks(dt * B1c), c3 = pks(dt * B3c), c4 = pks(dt * B4c),
                    c5 = pks(dt * B5c), c6 = pks(dt * B6c);
                #pragma unroll
                for (int p = 0; p < 8; p++) {
                    u64 aA = f2fma(c6, kAo[p], hA[p]);
                    u64 aB = f2fma(c6, kBo[p], hB[p]);
                    aA = f2fma(c5, k5A[p], aA);
                    aB = f2fma(c5, k5B[p], aB);
                    aA = f2fma(c4, k_ldA(sm, tid, 3, p), aA);
                    aB = f2fma(c4, k_ldB(sm, tid, 3, p), aB);
                    aA = f2fma(c3, k_ldA(sm, tid, 2, p), aA);
                    aB = f2fma(c3, k_ldB(sm, tid, 2, p), aB);
                    hA[p] = f2fma(c1, k_ldA(sm, tid, 0, p), aA);
                    hB[p] = f2fma(c1, k_ldB(sm, tid, 0, p), aB);
                }
            }
        }
        // readout
        {
            ulonglong2 wr0 = wrp[0], wr1 = wrp[1], wr2 = wrp[2], wr3 = wrp[3];
            u64 accA = f2mul(hA[0], wr0.x);  u64 accB = f2mul(hB[0], wr0.x);
            accA = f2fma(hA[1], wr0.y, accA); accB = f2fma(hB[1], wr0.y, accB);
            accA = f2fma(hA[2], wr1.x, accA); accB = f2fma(hB[2], wr1.x, accB);
            accA = f2fma(hA[3], wr1.y, accA); accB = f2fma(hB[3], wr1.y, accB);
            accA = f2fma(hA[4], wr2.x, accA); accB = f2fma(hB[4], wr2.x, accB);
            accA = f2fma(hA[5], wr2.y, accA); accB = f2fma(hB[5], wr2.y, accB);
            accA = f2fma(hA[6], wr3.x, accA); accB = f2fma(hB[6], wr3.x, accB);
            accA = f2fma(hA[7], wr3.y, accA); accB = f2fma(hB[7], wr3.y, accB);
            float lo, hi; upk(accA, lo, hi);
            out[rA * T_STEPS + step + 1] = fmaxf(sm[S_BR] + lo + hi, 0.0f);
            upk(accB, lo, hi);
            out[rB * T_STEPS + step + 1] = fmaxf(sm[S_BR] + lo + hi, 0.0f);
        }
    }
}

extern "C" void kernel_launch(void* const* d_in, const int* in_sizes, int n_in,
                              void* d_out, int out_size)
{
    (void)in_sizes; (void)n_in; (void)out_size;
    cudaFuncSetAttribute(neural_ode_66236985639756,
                         cudaFuncAttributeMaxDynamicSharedMemorySize,
                         S_TOTAL * sizeof(float));
    neural_ode_66236985639756<<<GRID, BLOCK, S_TOTAL * sizeof(float)>>>(
        (const float*)d_in[0],  // t
        (const float*)d_in[1],  // static_features
        (const float*)d_in[2],  // injection_times
        (const float*)d_in[3],  // injection_doses
        (const float*)d_in[4],  // W_se
        (const float*)d_in[5],  // b_se
        (const float*)d_in[6],  // W_i
        (const float*)d_in[7],  // b_i
        (const float*)d_in[8],  // W1
        (const float*)d_in[9],  // b1
        (const float*)d_in[10], // W2
        (const float*)d_in[11], // b2
        (const float*)d_in[12], // Wr
        (const float*)d_in[13], // br
        (float*)d_out);
}